// round 5
// baseline (speedup 1.0000x reference)
#include <cuda_runtime.h>
#include <math.h>

#define N_NODES 50000
#define N_EDGES 800000
#define INC 128
#define OUTC 64
#define TOT_E (N_EDGES + N_NODES)

// Scratch (allocation-free contract: __device__ globals)
__device__ float        g_xl[N_NODES * OUTC];   // 12.8 MB
__device__ float        g_xr[N_NODES * OUTC];   // 12.8 MB
__device__ float        g_logit[TOT_E];         // 3.4 MB
__device__ unsigned int g_maxkey[N_NODES];      // monotonic float keys
__device__ float        g_denom[N_NODES];

// Monotonic order-preserving float<->uint key (single atomic type, no punning)
__device__ __forceinline__ unsigned int f2key(float f) {
    unsigned int u = __float_as_uint(f);
    return (u & 0x80000000u) ? ~u : (u | 0x80000000u);
}
__device__ __forceinline__ float key2f(unsigned int k) {
    unsigned int u = (k & 0x80000000u) ? (k ^ 0x80000000u) : ~k;
    return __uint_as_float(u);
}

__global__ void k_init(float* __restrict__ out) {
    int i = blockIdx.x * blockDim.x + threadIdx.x;
    if (i < N_NODES * OUTC) out[i] = 0.0f;
    if (i < N_NODES) { g_maxkey[i] = 0u; g_denom[i] = 0.0f; }
}

// One block per node: threads 0..63 compute x_l row, 64..127 compute x_r row.
__global__ void k_gemm(const float* __restrict__ x,
                       const float* __restrict__ Wl,
                       const float* __restrict__ Wr) {
    __shared__ float xs[INC];
    int node = blockIdx.x;
    int t = threadIdx.x;
    xs[t] = x[node * INC + t];
    __syncthreads();
    const float* W = (t < OUTC) ? Wl : Wr;
    int c = t & (OUTC - 1);
    float acc = 0.0f;
#pragma unroll 8
    for (int k = 0; k < INC; k++)
        acc += xs[k] * W[k * OUTC + c];
    if (t < OUTC) g_xl[node * OUTC + c] = acc;
    else          g_xr[node * OUTC + c] = acc;
}

// Warp per edge: logit = att . leaky_relu(x_l[src] + x_r[dst]); running max per dst.
__global__ void k_edge1(const int* __restrict__ ei,
                        const float* __restrict__ att) {
    int e = (blockIdx.x * blockDim.x + threadIdx.x) >> 5;
    int lane = threadIdx.x & 31;
    if (e >= TOT_E) return;
    int s, d;
    if (e < N_EDGES) { s = ei[e]; d = ei[N_EDGES + e]; }
    else             { s = e - N_EDGES; d = s; }
    if ((unsigned)s >= N_NODES || (unsigned)d >= N_NODES) return;  // dtype safety net

    float v0 = g_xl[s * OUTC + lane]      + g_xr[d * OUTC + lane];
    float v1 = g_xl[s * OUTC + 32 + lane] + g_xr[d * OUTC + 32 + lane];
    v0 = (v0 > 0.0f ? v0 : 0.2f * v0) * att[lane];
    v1 = (v1 > 0.0f ? v1 : 0.2f * v1) * att[lane + 32];
    float sum = v0 + v1;
#pragma unroll
    for (int o = 16; o; o >>= 1) sum += __shfl_xor_sync(0xffffffffu, sum, o);
    if (lane == 0) {
        g_logit[e] = sum;
        atomicMax(&g_maxkey[d], f2key(sum));
    }
}

// Warp per edge: a = exp(logit - max[dst]); accumulate numerator + denom.
__global__ void k_edge2(const int* __restrict__ ei,
                        float* __restrict__ out) {
    int e = (blockIdx.x * blockDim.x + threadIdx.x) >> 5;
    int lane = threadIdx.x & 31;
    if (e >= TOT_E) return;
    int s, d;
    if (e < N_EDGES) { s = ei[e]; d = ei[N_EDGES + e]; }
    else             { s = e - N_EDGES; d = s; }
    if ((unsigned)s >= N_NODES || (unsigned)d >= N_NODES) return;  // dtype safety net

    float m = key2f(g_maxkey[d]);   // every node has a self-loop -> always finite
    float a = expf(g_logit[e] - m);
    if (lane == 0) atomicAdd(&g_denom[d], a);
    atomicAdd(&out[d * OUTC + lane],      g_xl[s * OUTC + lane]      * a);
    atomicAdd(&out[d * OUTC + 32 + lane], g_xl[s * OUTC + 32 + lane] * a);
}

// Warp per node: out = log_softmax(elu(acc/denom + bias)), in-place.
__global__ void k_final(const float* __restrict__ bias,
                        float* __restrict__ out) {
    int n = (blockIdx.x * blockDim.x + threadIdx.x) >> 5;
    int lane = threadIdx.x & 31;
    if (n >= N_NODES) return;
    float inv = 1.0f / (g_denom[n] + 1e-16f);
    float h0 = out[n * OUTC + lane]      * inv + bias[lane];
    float h1 = out[n * OUTC + 32 + lane] * inv + bias[lane + 32];
    h0 = h0 > 0.0f ? h0 : expm1f(h0);
    h1 = h1 > 0.0f ? h1 : expm1f(h1);
    float m = fmaxf(h0, h1);
#pragma unroll
    for (int o = 16; o; o >>= 1) m = fmaxf(m, __shfl_xor_sync(0xffffffffu, m, o));
    float sme = expf(h0 - m) + expf(h1 - m);
#pragma unroll
    for (int o = 16; o; o >>= 1) sme += __shfl_xor_sync(0xffffffffu, sme, o);
    float ls = m + logf(sme);
    out[n * OUTC + lane]      = h0 - ls;
    out[n * OUTC + 32 + lane] = h1 - ls;
}

extern "C" void kernel_launch(void* const* d_in, const int* in_sizes, int n_in,
                              void* d_out, int out_size) {
    const float* x    = (const float*)d_in[0];
    const int*   ei   = (const int*)d_in[1];     // edge_index is int32 (JAX x64 disabled)
    const float* Wl   = (const float*)d_in[2];
    const float* Wr   = (const float*)d_in[3];
    const float* att  = (const float*)d_in[4];
    const float* bias = (const float*)d_in[5];
    float*       out  = (float*)d_out;

    k_init<<<(N_NODES * OUTC + 255) / 256, 256>>>(out);
    k_gemm<<<N_NODES, INC>>>(x, Wl, Wr);
    {
        long long thr = (long long)TOT_E * 32;
        k_edge1<<<(unsigned)((thr + 255) / 256), 256>>>(ei, att);
        k_edge2<<<(unsigned)((thr + 255) / 256), 256>>>(ei, out);
    }
    {
        long long thr = (long long)N_NODES * 32;
        k_final<<<(unsigned)((thr + 255) / 256), 256>>>(bias, out);
    }
}

// round 7
// speedup vs baseline: 1.1705x; 1.1705x over previous
#include <cuda_runtime.h>
#include <math.h>

#define N_NODES 50000
#define N_EDGES 800000
#define INC 128
#define OUTC 64
#define TOT_E (N_EDGES + N_NODES)
#define SCAN_T 1024

// Scratch (__device__ globals per allocation-free contract)
__device__ float g_xl[N_NODES * OUTC];   // 12.8 MB
__device__ float g_xr[N_NODES * OUTC];   // 12.8 MB
__device__ int   g_deg[N_NODES];
__device__ int   g_off[N_NODES + 1];
__device__ int   g_cur[N_NODES];
__device__ int   g_src[TOT_E];           // CSR: source ids grouped by dst

__global__ void k_zero() {
    int i = blockIdx.x * blockDim.x + threadIdx.x;
    if (i < N_NODES) g_deg[i] = 0;
}

// Degree histogram over dst (incl. self-loops)
__global__ void k_hist(const int* __restrict__ ei) {
    int e = blockIdx.x * blockDim.x + threadIdx.x;
    if (e >= TOT_E) return;
    int d = (e < N_EDGES) ? ei[N_EDGES + e] : (e - N_EDGES);
    atomicAdd(&g_deg[d], 1);
}

// Single-block exclusive scan of g_deg -> g_off (N=50K, ~49 chunks of 1024)
__global__ void k_scan() {
    __shared__ int sh[SCAN_T];
    __shared__ int run;
    int t = threadIdx.x;
    if (t == 0) run = 0;
    __syncthreads();
    for (int base = 0; base < N_NODES; base += SCAN_T) {
        int i = base + t;
        int v = (i < N_NODES) ? g_deg[i] : 0;
        sh[t] = v;
        __syncthreads();
#pragma unroll
        for (int o = 1; o < SCAN_T; o <<= 1) {
            int tv = (t >= o) ? sh[t - o] : 0;
            __syncthreads();
            sh[t] += tv;
            __syncthreads();
        }
        if (i < N_NODES) {
            int off = run + sh[t] - v;
            g_off[i] = off;
            g_cur[i] = off;
        }
        __syncthreads();
        if (t == 0) run += sh[SCAN_T - 1];
        __syncthreads();
    }
    if (t == 0) g_off[N_NODES] = run;
}

// Scatter: bucket src ids by dst
__global__ void k_scatter(const int* __restrict__ ei) {
    int e = blockIdx.x * blockDim.x + threadIdx.x;
    if (e >= TOT_E) return;
    int s, d;
    if (e < N_EDGES) { s = ei[e]; d = ei[N_EDGES + e]; }
    else             { s = e - N_EDGES; d = s; }
    int pos = atomicAdd(&g_cur[d], 1);
    g_src[pos] = s;
}

// One block per node: threads 0..63 compute x_l row, 64..127 compute x_r row.
__global__ void k_gemm(const float* __restrict__ x,
                       const float* __restrict__ Wl,
                       const float* __restrict__ Wr) {
    __shared__ float xs[INC];
    int node = blockIdx.x;
    int t = threadIdx.x;
    xs[t] = x[node * INC + t];
    __syncthreads();
    const float* W = (t < OUTC) ? Wl : Wr;
    int c = t & (OUTC - 1);
    float acc = 0.0f;
#pragma unroll 8
    for (int k = 0; k < INC; k++)
        acc += xs[k] * W[k * OUTC + c];
    if (t < OUTC) g_xl[node * OUTC + c] = acc;
    else          g_xr[node * OUTC + c] = acc;
}

// Warp per dst node: online-softmax aggregation over CSR edges, then
// ELU + log_softmax epilogue. No atomics, single pass over edges.
__global__ void k_node(const float* __restrict__ att,
                       const float* __restrict__ bias,
                       float* __restrict__ out) {
    int n = (blockIdx.x * blockDim.x + threadIdx.x) >> 5;
    int lane = threadIdx.x & 31;
    if (n >= N_NODES) return;

    float a0 = att[lane], a1 = att[lane + 32];
    float xr0 = g_xr[n * OUTC + lane];
    float xr1 = g_xr[n * OUTC + 32 + lane];
    int e = g_off[n], end = g_off[n + 1];

    float m = -INFINITY, den = 0.0f, acc0 = 0.0f, acc1 = 0.0f;
    for (; e < end; e++) {
        int s = g_src[e];
        float xl0 = g_xl[s * OUTC + lane];
        float xl1 = g_xl[s * OUTC + 32 + lane];
        float v0 = xl0 + xr0; v0 = (v0 > 0.0f ? v0 : 0.2f * v0) * a0;
        float v1 = xl1 + xr1; v1 = (v1 > 0.0f ? v1 : 0.2f * v1) * a1;
        float sum = v0 + v1;
#pragma unroll
        for (int o = 16; o; o >>= 1) sum += __shfl_xor_sync(0xffffffffu, sum, o);
        float mn = fmaxf(m, sum);
        float sc = __expf(m - mn);     // first iter: __expf(-inf)=0
        float w  = __expf(sum - mn);
        den  = den  * sc + w;
        acc0 = acc0 * sc + w * xl0;
        acc1 = acc1 * sc + w * xl1;
        m = mn;
    }

    float inv = 1.0f / den;            // den>0: every node has a self-loop
    float h0 = acc0 * inv + bias[lane];
    float h1 = acc1 * inv + bias[lane + 32];
    h0 = h0 > 0.0f ? h0 : __expf(h0) - 1.0f;
    h1 = h1 > 0.0f ? h1 : __expf(h1) - 1.0f;
    float mx = fmaxf(h0, h1);
#pragma unroll
    for (int o = 16; o; o >>= 1) mx = fmaxf(mx, __shfl_xor_sync(0xffffffffu, mx, o));
    float sme = __expf(h0 - mx) + __expf(h1 - mx);
#pragma unroll
    for (int o = 16; o; o >>= 1) sme += __shfl_xor_sync(0xffffffffu, sme, o);
    float ls = mx + __logf(sme);
    out[n * OUTC + lane]      = h0 - ls;
    out[n * OUTC + 32 + lane] = h1 - ls;
}

extern "C" void kernel_launch(void* const* d_in, const int* in_sizes, int n_in,
                              void* d_out, int out_size) {
    const float* x    = (const float*)d_in[0];
    const int*   ei   = (const int*)d_in[1];   // int32 (JAX x64 disabled)
    const float* Wl   = (const float*)d_in[2];
    const float* Wr   = (const float*)d_in[3];
    const float* att  = (const float*)d_in[4];
    const float* bias = (const float*)d_in[5];
    float*       out  = (float*)d_out;

    k_zero<<<(N_NODES + 255) / 256, 256>>>();
    k_hist<<<(TOT_E + 255) / 256, 256>>>(ei);
    k_scan<<<1, SCAN_T>>>();
    k_scatter<<<(TOT_E + 255) / 256, 256>>>(ei);
    k_gemm<<<N_NODES, INC>>>(x, Wl, Wr);
    k_node<<<(N_NODES * 32 + 255) / 256, 256>>>(att, bias, out);
}

// round 10
// speedup vs baseline: 1.2309x; 1.0516x over previous
#include <cuda_runtime.h>
#include <math.h>

#define N_NODES 50000
#define N_EDGES 800000
#define INC 128
#define OUTC 64
#define TOT_E (N_EDGES + N_NODES)
#define SCAN_T 1024

// Scratch (__device__ globals per allocation-free contract)
__device__ float g_xl[N_NODES * OUTC];   // 12.8 MB
__device__ float g_xr[N_NODES * OUTC];   // 12.8 MB
__device__ int   g_deg[N_NODES];
__device__ int   g_off[N_NODES + 1];
__device__ int   g_cur[N_NODES];
__device__ int   g_src[TOT_E];           // CSR: source ids grouped by dst

__global__ void k_zero() {
    int i = blockIdx.x * blockDim.x + threadIdx.x;
    if (i < N_NODES) g_deg[i] = 0;
}

// Degree histogram over dst, 4 independent edges per thread for MLP.
__global__ void k_hist(const int* __restrict__ ei) {
    int t = blockIdx.x * blockDim.x + threadIdx.x;
    int stride = gridDim.x * blockDim.x;
#pragma unroll
    for (int i = 0; i < 4; i++) {
        int e = t + i * stride;
        if (e < TOT_E) {
            int d = (e < N_EDGES) ? ei[N_EDGES + e] : (e - N_EDGES);
            atomicAdd(&g_deg[d], 1);
        }
    }
}

// Hierarchical single-block exclusive scan: thread-serial chunks + warp scan.
__global__ void k_scan() {
    const int CH = (N_NODES + SCAN_T - 1) / SCAN_T;  // 49
    int t = threadIdx.x;
    int lane = t & 31, wid = t >> 5;
    int base = t * CH;

    int sum = 0;
    for (int i = 0; i < CH; i++) {
        int idx = base + i;
        if (idx < N_NODES) sum += g_deg[idx];
    }
    // block exclusive scan of per-thread sums
    int incl = sum;
#pragma unroll
    for (int o = 1; o < 32; o <<= 1) {
        int v = __shfl_up_sync(0xffffffffu, incl, o);
        if (lane >= o) incl += v;
    }
    __shared__ int ws[32];
    if (lane == 31) ws[wid] = incl;
    __syncthreads();
    if (wid == 0) {
        int w = ws[lane];
#pragma unroll
        for (int o = 1; o < 32; o <<= 1) {
            int v = __shfl_up_sync(0xffffffffu, w, o);
            if (lane >= o) w += v;
        }
        ws[lane] = w;
    }
    __syncthreads();
    int run = incl - sum + (wid ? ws[wid - 1] : 0);

    for (int i = 0; i < CH; i++) {
        int idx = base + i;
        if (idx < N_NODES) {
            g_off[idx] = run;
            g_cur[idx] = run;
            run += g_deg[idx];
        }
    }
    if (t == SCAN_T - 1) g_off[N_NODES] = ws[31];
}

// Scatter src ids by dst, 4 independent edges per thread.
__global__ void k_scatter(const int* __restrict__ ei) {
    int t = blockIdx.x * blockDim.x + threadIdx.x;
    int stride = gridDim.x * blockDim.x;
#pragma unroll
    for (int i = 0; i < 4; i++) {
        int e = t + i * stride;
        if (e < TOT_E) {
            int s, d;
            if (e < N_EDGES) { s = ei[e]; d = ei[N_EDGES + e]; }
            else             { s = e - N_EDGES; d = s; }
            int pos = atomicAdd(&g_cur[d], 1);
            g_src[pos] = s;
        }
    }
}

// One block per node: threads 0..63 -> x_l row, 64..127 -> x_r row.
__global__ void k_gemm(const float* __restrict__ x,
                       const float* __restrict__ Wl,
                       const float* __restrict__ Wr) {
    __shared__ float xs[INC];
    int node = blockIdx.x;
    int t = threadIdx.x;
    xs[t] = x[node * INC + t];
    __syncthreads();
    const float* W = (t < OUTC) ? Wl : Wr;
    int c = t & (OUTC - 1);
    float acc = 0.0f;
#pragma unroll 8
    for (int k = 0; k < INC; k++)
        acc += xs[k] * W[k * OUTC + c];
    if (t < OUTC) g_xl[node * OUTC + c] = acc;
    else          g_xr[node * OUTC + c] = acc;
}

__device__ __forceinline__ float lrelu(float v) { return v > 0.0f ? v : 0.2f * v; }

// Warp per dst node: 4-way unrolled online-softmax aggregation + epilogue.
__global__ void k_node(const float* __restrict__ att,
                       const float* __restrict__ bias,
                       float* __restrict__ out) {
    int n = (blockIdx.x * blockDim.x + threadIdx.x) >> 5;
    int lane = threadIdx.x & 31;
    if (n >= N_NODES) return;

    float a0 = att[lane], a1 = att[lane + 32];
    float xr0 = g_xr[n * OUTC + lane];
    float xr1 = g_xr[n * OUTC + 32 + lane];
    int e = g_off[n], end = g_off[n + 1];

    float m = -INFINITY, den = 0.0f, acc0 = 0.0f, acc1 = 0.0f;

    for (; e + 4 <= end; e += 4) {
        int s0 = g_src[e], s1 = g_src[e + 1], s2 = g_src[e + 2], s3 = g_src[e + 3];
        float x00 = g_xl[s0 * OUTC + lane], x01 = g_xl[s0 * OUTC + 32 + lane];
        float x10 = g_xl[s1 * OUTC + lane], x11 = g_xl[s1 * OUTC + 32 + lane];
        float x20 = g_xl[s2 * OUTC + lane], x21 = g_xl[s2 * OUTC + 32 + lane];
        float x30 = g_xl[s3 * OUTC + lane], x31 = g_xl[s3 * OUTC + 32 + lane];

        float t0 = lrelu(x00 + xr0) * a0 + lrelu(x01 + xr1) * a1;
        float t1 = lrelu(x10 + xr0) * a0 + lrelu(x11 + xr1) * a1;
        float t2 = lrelu(x20 + xr0) * a0 + lrelu(x21 + xr1) * a1;
        float t3 = lrelu(x30 + xr0) * a0 + lrelu(x31 + xr1) * a1;
#pragma unroll
        for (int o = 16; o; o >>= 1) {
            t0 += __shfl_xor_sync(0xffffffffu, t0, o);
            t1 += __shfl_xor_sync(0xffffffffu, t1, o);
            t2 += __shfl_xor_sync(0xffffffffu, t2, o);
            t3 += __shfl_xor_sync(0xffffffffu, t3, o);
        }
        float bm = fmaxf(fmaxf(t0, t1), fmaxf(t2, t3));
        float mn = fmaxf(m, bm);
        float sc = __expf(m - mn);         // first batch: __expf(-inf)=0
        float w0 = __expf(t0 - mn), w1 = __expf(t1 - mn);
        float w2 = __expf(t2 - mn), w3 = __expf(t3 - mn);
        den  = den  * sc + ((w0 + w1) + (w2 + w3));
        acc0 = acc0 * sc + (w0 * x00 + w1 * x10 + w2 * x20 + w3 * x30);
        acc1 = acc1 * sc + (w0 * x01 + w1 * x11 + w2 * x21 + w3 * x31);
        m = mn;
    }
    for (; e < end; e++) {
        int s = g_src[e];
        float xl0 = g_xl[s * OUTC + lane];
        float xl1 = g_xl[s * OUTC + 32 + lane];
        float t0 = lrelu(xl0 + xr0) * a0 + lrelu(xl1 + xr1) * a1;
#pragma unroll
        for (int o = 16; o; o >>= 1) t0 += __shfl_xor_sync(0xffffffffu, t0, o);
        float mn = fmaxf(m, t0);
        float sc = __expf(m - mn);
        float w  = __expf(t0 - mn);
        den  = den  * sc + w;
        acc0 = acc0 * sc + w * xl0;
        acc1 = acc1 * sc + w * xl1;
        m = mn;
    }

    float inv = 1.0f / den;                // den>0: self-loop guarantees an edge
    float h0 = acc0 * inv + bias[lane];
    float h1 = acc1 * inv + bias[lane + 32];
    h0 = h0 > 0.0f ? h0 : __expf(h0) - 1.0f;
    h1 = h1 > 0.0f ? h1 : __expf(h1) - 1.0f;
    float mx = fmaxf(h0, h1);
#pragma unroll
    for (int o = 16; o; o >>= 1) mx = fmaxf(mx, __shfl_xor_sync(0xffffffffu, mx, o));
    float sme = __expf(h0 - mx) + __expf(h1 - mx);
#pragma unroll
    for (int o = 16; o; o >>= 1) sme += __shfl_xor_sync(0xffffffffu, sme, o);
    float ls = mx + __logf(sme);
    out[n * OUTC + lane]      = h0 - ls;
    out[n * OUTC + 32 + lane] = h1 - ls;
}

extern "C" void kernel_launch(void* const* d_in, const int* in_sizes, int n_in,
                              void* d_out, int out_size) {
    const float* x    = (const float*)d_in[0];
    const int*   ei   = (const int*)d_in[1];   // int32 (JAX x64 disabled)
    const float* Wl   = (const float*)d_in[2];
    const float* Wr   = (const float*)d_in[3];
    const float* att  = (const float*)d_in[4];
    const float* bias = (const float*)d_in[5];
    float*       out  = (float*)d_out;

    // Linear launch order on the default stream (no fork/join: capture-safe).
    k_gemm<<<N_NODES, INC>>>(x, Wl, Wr);
    k_zero<<<(N_NODES + 255) / 256, 256>>>();
    {
        int thr = (TOT_E + 3) / 4;
        k_hist<<<(thr + 255) / 256, 256>>>(ei);
    }
    k_scan<<<1, SCAN_T>>>();
    {
        int thr = (TOT_E + 3) / 4;
        k_scatter<<<(thr + 255) / 256, 256>>>(ei);
    }
    k_node<<<(N_NODES * 32 + 255) / 256, 256>>>(att, bias, out);
}

// round 13
// speedup vs baseline: 1.6537x; 1.3435x over previous
#include <cuda_runtime.h>
#include <math.h>

#define N_NODES 50000
#define N_EDGES 800000
#define INC 128
#define OUTC 64
#define TOT_E (N_EDGES + N_NODES)
#define NBLK ((N_NODES + 255) / 256)   // 196 scan blocks

// Scratch (__device__ globals per allocation-free contract)
__device__ float g_xl[N_NODES * OUTC];   // 12.8 MB
__device__ float g_xr[N_NODES * OUTC];   // 12.8 MB
__device__ int   g_deg[N_NODES];
__device__ int   g_off[N_NODES + 1];
__device__ int   g_cur[N_NODES];
__device__ int   g_src[TOT_E];           // CSR: source ids grouped by dst
__device__ int   g_bsum[NBLK];
__device__ int   g_boff[NBLK];

__global__ void k_zero() {
    int i = blockIdx.x * blockDim.x + threadIdx.x;
    if (i < N_NODES) g_deg[i] = 0;
}

// Degree histogram over dst, 4 independent edges per thread for MLP.
__global__ void k_hist(const int* __restrict__ ei) {
    int t = blockIdx.x * blockDim.x + threadIdx.x;
    int stride = gridDim.x * blockDim.x;
#pragma unroll
    for (int i = 0; i < 4; i++) {
        int e = t + i * stride;
        if (e < TOT_E) {
            int d = (e < N_EDGES) ? ei[N_EDGES + e] : (e - N_EDGES);
            atomicAdd(&g_deg[d], 1);
        }
    }
}

// ---- chip-wide 3-phase exclusive scan of g_deg -> g_off ----

// Phase 1: per-block sums.
__global__ void k_part() {
    int i = blockIdx.x * 256 + threadIdx.x;
    int lane = threadIdx.x & 31, wid = threadIdx.x >> 5;
    int v = (i < N_NODES) ? g_deg[i] : 0;
#pragma unroll
    for (int o = 16; o; o >>= 1) v += __shfl_xor_sync(0xffffffffu, v, o);
    __shared__ int ws[8];
    if (lane == 0) ws[wid] = v;
    __syncthreads();
    if (threadIdx.x == 0) {
        int s = 0;
#pragma unroll
        for (int w = 0; w < 8; w++) s += ws[w];
        g_bsum[blockIdx.x] = s;
    }
}

// Phase 2: single block scans the 196 block sums (exclusive).
__global__ void k_bscan() {
    int t = threadIdx.x;
    int lane = t & 31, wid = t >> 5;
    int v = (t < NBLK) ? g_bsum[t] : 0;
    int incl = v;
#pragma unroll
    for (int o = 1; o < 32; o <<= 1) {
        int u = __shfl_up_sync(0xffffffffu, incl, o);
        if (lane >= o) incl += u;
    }
    __shared__ int ws[8];
    if (lane == 31) ws[wid] = incl;
    __syncthreads();
    int woff = 0;
#pragma unroll
    for (int w = 0; w < 8; w++) woff += (w < wid) ? ws[w] : 0;
    int excl = woff + incl - v;
    if (t < NBLK) g_boff[t] = excl;
    if (t == NBLK - 1) g_off[N_NODES] = excl + v;
}

// Phase 3: block-local exclusive scan + block offset -> g_off, g_cur.
__global__ void k_off() {
    int i = blockIdx.x * 256 + threadIdx.x;
    int lane = threadIdx.x & 31, wid = threadIdx.x >> 5;
    int v = (i < N_NODES) ? g_deg[i] : 0;
    int incl = v;
#pragma unroll
    for (int o = 1; o < 32; o <<= 1) {
        int u = __shfl_up_sync(0xffffffffu, incl, o);
        if (lane >= o) incl += u;
    }
    __shared__ int ws[8];
    if (lane == 31) ws[wid] = incl;
    __syncthreads();
    int woff = 0;
#pragma unroll
    for (int w = 0; w < 8; w++) woff += (w < wid) ? ws[w] : 0;
    int excl = g_boff[blockIdx.x] + woff + incl - v;
    if (i < N_NODES) { g_off[i] = excl; g_cur[i] = excl; }
}

// Scatter src ids by dst, 4 independent edges per thread.
__global__ void k_scatter(const int* __restrict__ ei) {
    int t = blockIdx.x * blockDim.x + threadIdx.x;
    int stride = gridDim.x * blockDim.x;
#pragma unroll
    for (int i = 0; i < 4; i++) {
        int e = t + i * stride;
        if (e < TOT_E) {
            int s, d;
            if (e < N_EDGES) { s = ei[e]; d = ei[N_EDGES + e]; }
            else             { s = e - N_EDGES; d = s; }
            int pos = atomicAdd(&g_cur[d], 1);
            g_src[pos] = s;
        }
    }
}

// One block per node: threads 0..63 -> x_l row, 64..127 -> x_r row.
__global__ void k_gemm(const float* __restrict__ x,
                       const float* __restrict__ Wl,
                       const float* __restrict__ Wr) {
    __shared__ float xs[INC];
    int node = blockIdx.x;
    int t = threadIdx.x;
    xs[t] = x[node * INC + t];
    __syncthreads();
    const float* W = (t < OUTC) ? Wl : Wr;
    int c = t & (OUTC - 1);
    float acc = 0.0f;
#pragma unroll 8
    for (int k = 0; k < INC; k++)
        acc += xs[k] * W[k * OUTC + c];
    if (t < OUTC) g_xl[node * OUTC + c] = acc;
    else          g_xr[node * OUTC + c] = acc;
}

__device__ __forceinline__ float lrelu(float v) { return v > 0.0f ? v : 0.2f * v; }

// Warp per dst node: 4-way unrolled online-softmax aggregation + epilogue.
__global__ void k_node(const float* __restrict__ att,
                       const float* __restrict__ bias,
                       float* __restrict__ out) {
    int n = (blockIdx.x * blockDim.x + threadIdx.x) >> 5;
    int lane = threadIdx.x & 31;
    if (n >= N_NODES) return;

    float a0 = att[lane], a1 = att[lane + 32];
    float xr0 = g_xr[n * OUTC + lane];
    float xr1 = g_xr[n * OUTC + 32 + lane];
    int e = g_off[n], end = g_off[n + 1];

    float m = -INFINITY, den = 0.0f, acc0 = 0.0f, acc1 = 0.0f;

    for (; e + 4 <= end; e += 4) {
        int s0 = g_src[e], s1 = g_src[e + 1], s2 = g_src[e + 2], s3 = g_src[e + 3];
        float x00 = g_xl[s0 * OUTC + lane], x01 = g_xl[s0 * OUTC + 32 + lane];
        float x10 = g_xl[s1 * OUTC + lane], x11 = g_xl[s1 * OUTC + 32 + lane];
        float x20 = g_xl[s2 * OUTC + lane], x21 = g_xl[s2 * OUTC + 32 + lane];
        float x30 = g_xl[s3 * OUTC + lane], x31 = g_xl[s3 * OUTC + 32 + lane];

        float t0 = lrelu(x00 + xr0) * a0 + lrelu(x01 + xr1) * a1;
        float t1 = lrelu(x10 + xr0) * a0 + lrelu(x11 + xr1) * a1;
        float t2 = lrelu(x20 + xr0) * a0 + lrelu(x21 + xr1) * a1;
        float t3 = lrelu(x30 + xr0) * a0 + lrelu(x31 + xr1) * a1;
#pragma unroll
        for (int o = 16; o; o >>= 1) {
            t0 += __shfl_xor_sync(0xffffffffu, t0, o);
            t1 += __shfl_xor_sync(0xffffffffu, t1, o);
            t2 += __shfl_xor_sync(0xffffffffu, t2, o);
            t3 += __shfl_xor_sync(0xffffffffu, t3, o);
        }
        float bm = fmaxf(fmaxf(t0, t1), fmaxf(t2, t3));
        float mn = fmaxf(m, bm);
        float sc = __expf(m - mn);         // first batch: __expf(-inf)=0
        float w0 = __expf(t0 - mn), w1 = __expf(t1 - mn);
        float w2 = __expf(t2 - mn), w3 = __expf(t3 - mn);
        den  = den  * sc + ((w0 + w1) + (w2 + w3));
        acc0 = acc0 * sc + (w0 * x00 + w1 * x10 + w2 * x20 + w3 * x30);
        acc1 = acc1 * sc + (w0 * x01 + w1 * x11 + w2 * x21 + w3 * x31);
        m = mn;
    }
    for (; e < end; e++) {
        int s = g_src[e];
        float xl0 = g_xl[s * OUTC + lane];
        float xl1 = g_xl[s * OUTC + 32 + lane];
        float t0 = lrelu(xl0 + xr0) * a0 + lrelu(xl1 + xr1) * a1;
#pragma unroll
        for (int o = 16; o; o >>= 1) t0 += __shfl_xor_sync(0xffffffffu, t0, o);
        float mn = fmaxf(m, t0);
        float sc = __expf(m - mn);
        float w  = __expf(t0 - mn);
        den  = den  * sc + w;
        acc0 = acc0 * sc + w * xl0;
        acc1 = acc1 * sc + w * xl1;
        m = mn;
    }

    float inv = 1.0f / den;                // den>0: self-loop guarantees an edge
    float h0 = acc0 * inv + bias[lane];
    float h1 = acc1 * inv + bias[lane + 32];
    h0 = h0 > 0.0f ? h0 : __expf(h0) - 1.0f;
    h1 = h1 > 0.0f ? h1 : __expf(h1) - 1.0f;
    float mx = fmaxf(h0, h1);
#pragma unroll
    for (int o = 16; o; o >>= 1) mx = fmaxf(mx, __shfl_xor_sync(0xffffffffu, mx, o));
    float sme = __expf(h0 - mx) + __expf(h1 - mx);
#pragma unroll
    for (int o = 16; o; o >>= 1) sme += __shfl_xor_sync(0xffffffffu, sme, o);
    float ls = mx + __logf(sme);
    out[n * OUTC + lane]      = h0 - ls;
    out[n * OUTC + 32 + lane] = h1 - ls;
}

extern "C" void kernel_launch(void* const* d_in, const int* in_sizes, int n_in,
                              void* d_out, int out_size) {
    const float* x    = (const float*)d_in[0];
    const int*   ei   = (const int*)d_in[1];   // int32 (JAX x64 disabled)
    const float* Wl   = (const float*)d_in[2];
    const float* Wr   = (const float*)d_in[3];
    const float* att  = (const float*)d_in[4];
    const float* bias = (const float*)d_in[5];
    float*       out  = (float*)d_out;

    // Linear launch order on the default stream (capture-safe).
    k_gemm<<<N_NODES, INC>>>(x, Wl, Wr);
    k_zero<<<(N_NODES + 255) / 256, 256>>>();
    {
        int thr = (TOT_E + 3) / 4;
        k_hist<<<(thr + 255) / 256, 256>>>(ei);
    }
    k_part<<<NBLK, 256>>>();
    k_bscan<<<1, 256>>>();
    k_off<<<NBLK, 256>>>();
    {
        int thr = (TOT_E + 3) / 4;
        k_scatter<<<(thr + 255) / 256, 256>>>(ei);
    }
    k_node<<<(N_NODES * 32 + 255) / 256, 256>>>(att, bias, out);
}

// round 15
// speedup vs baseline: 2.7836x; 1.6833x over previous
#include <cuda_runtime.h>
#include <math.h>

#define N_NODES 50000
#define N_EDGES 800000
#define INC 128
#define OUTC 64
#define TOT_E (N_EDGES + N_NODES)
#define NBLK ((N_NODES + 255) / 256)   // 196 scan blocks
#define GN 32                          // gemm nodes per block

// Scratch (__device__ globals per allocation-free contract)
__device__ float g_xl[N_NODES * OUTC];   // 12.8 MB
__device__ float g_xr[N_NODES * OUTC];   // 12.8 MB
__device__ int   g_deg[N_NODES];         // zero-init at load; re-zeroed by k_off
__device__ int   g_off[N_NODES + 1];
__device__ int   g_cur[N_NODES];
__device__ int   g_src[TOT_E];           // CSR: source ids grouped by dst
__device__ int   g_bsum[NBLK];
__device__ int   g_boff[NBLK];

// Degree histogram over dst, 4 independent edges per thread for MLP.
__global__ void k_hist(const int* __restrict__ ei) {
    int t = blockIdx.x * blockDim.x + threadIdx.x;
    int stride = gridDim.x * blockDim.x;
#pragma unroll
    for (int i = 0; i < 4; i++) {
        int e = t + i * stride;
        if (e < TOT_E) {
            int d = (e < N_EDGES) ? ei[N_EDGES + e] : (e - N_EDGES);
            atomicAdd(&g_deg[d], 1);
        }
    }
}

// ---- chip-wide 3-phase exclusive scan of g_deg -> g_off ----
__global__ void k_part() {
    int i = blockIdx.x * 256 + threadIdx.x;
    int lane = threadIdx.x & 31, wid = threadIdx.x >> 5;
    int v = (i < N_NODES) ? g_deg[i] : 0;
#pragma unroll
    for (int o = 16; o; o >>= 1) v += __shfl_xor_sync(0xffffffffu, v, o);
    __shared__ int ws[8];
    if (lane == 0) ws[wid] = v;
    __syncthreads();
    if (threadIdx.x == 0) {
        int s = 0;
#pragma unroll
        for (int w = 0; w < 8; w++) s += ws[w];
        g_bsum[blockIdx.x] = s;
    }
}

__global__ void k_bscan() {
    int t = threadIdx.x;
    int lane = t & 31, wid = t >> 5;
    int v = (t < NBLK) ? g_bsum[t] : 0;
    int incl = v;
#pragma unroll
    for (int o = 1; o < 32; o <<= 1) {
        int u = __shfl_up_sync(0xffffffffu, incl, o);
        if (lane >= o) incl += u;
    }
    __shared__ int ws[8];
    if (lane == 31) ws[wid] = incl;
    __syncthreads();
    int woff = 0;
#pragma unroll
    for (int w = 0; w < 8; w++) woff += (w < wid) ? ws[w] : 0;
    int excl = woff + incl - v;
    if (t < NBLK) g_boff[t] = excl;
    if (t == NBLK - 1) g_off[N_NODES] = excl + v;
}

// Phase 3: offsets; also re-zeroes g_deg for the next graph replay.
__global__ void k_off() {
    int i = blockIdx.x * 256 + threadIdx.x;
    int lane = threadIdx.x & 31, wid = threadIdx.x >> 5;
    int v = (i < N_NODES) ? g_deg[i] : 0;
    int incl = v;
#pragma unroll
    for (int o = 1; o < 32; o <<= 1) {
        int u = __shfl_up_sync(0xffffffffu, incl, o);
        if (lane >= o) incl += u;
    }
    __shared__ int ws[8];
    if (lane == 31) ws[wid] = incl;
    __syncthreads();
    int woff = 0;
#pragma unroll
    for (int w = 0; w < 8; w++) woff += (w < wid) ? ws[w] : 0;
    int excl = g_boff[blockIdx.x] + woff + incl - v;
    if (i < N_NODES) {
        g_off[i] = excl;
        g_cur[i] = excl;
        g_deg[i] = 0;          // ready for next replay's k_hist
    }
}

// Scatter src ids by dst, 4 independent edges per thread.
__global__ void k_scatter(const int* __restrict__ ei) {
    int t = blockIdx.x * blockDim.x + threadIdx.x;
    int stride = gridDim.x * blockDim.x;
#pragma unroll
    for (int i = 0; i < 4; i++) {
        int e = t + i * stride;
        if (e < TOT_E) {
            int s, d;
            if (e < N_EDGES) { s = ei[e]; d = ei[N_EDGES + e]; }
            else             { s = e - N_EDGES; d = s; }
            int pos = atomicAdd(&g_cur[d], 1);
            g_src[pos] = s;
        }
    }
}

// Packed fp32x2 FMA (sm_103a FFMA2) helpers
__device__ __forceinline__ void fma2(unsigned long long& d,
                                     unsigned long long a,
                                     unsigned long long b,
                                     unsigned long long c) {
    asm("fma.rn.f32x2 %0, %1, %2, %3;" : "=l"(d) : "l"(a), "l"(b), "l"(c));
}
__device__ __forceinline__ unsigned long long pack2(float lo, float hi) {
    unsigned long long r;
    asm("mov.b64 %0, {%1, %2};" : "=l"(r) : "f"(lo), "f"(hi));
    return r;
}
__device__ __forceinline__ void unpack2(float& lo, float& hi, unsigned long long v) {
    asm("mov.b64 {%0, %1}, %2;" : "=f"(lo), "=f"(hi) : "l"(v));
}

// Tiled transform: grid (ceil(N/GN), 2); y=0 -> W_l/g_xl, y=1 -> W_r/g_xr.
// 128 threads: 16 col-threads (4 cols each) x 8 groups (4 nodes each).
// f32x2 accumulators over col pairs; W pairs load directly as 64-bit LDS.
__global__ void k_gemm(const float* __restrict__ x,
                       const float* __restrict__ Wl,
                       const float* __restrict__ Wr) {
    __shared__ float Ws[INC * OUTC];     // 32 KB
    __shared__ float xs[GN][INC];        // 16 KB
    const float* W = blockIdx.y ? Wr : Wl;
    float* outp = blockIdx.y ? g_xr : g_xl;
    int t = threadIdx.x;
    int base = blockIdx.x * GN;

    {   // load W (8192 floats) via float4
        const float4* W4 = (const float4*)W;
        float4* Ws4 = (float4*)Ws;
#pragma unroll
        for (int i = 0; i < (INC * OUTC / 4) / 128; i++)
            Ws4[t + i * 128] = W4[t + i * 128];
    }
    {   // load x tile (GN*INC floats) via float4, zero-pad OOB nodes
        float4* xs4 = (float4*)&xs[0][0];
        const float4* x4 = (const float4*)x;
#pragma unroll
        for (int i = 0; i < (GN * INC / 4) / 128; i++) {
            int idx = t + i * 128;
            int node = base + idx / (INC / 4);
            xs4[idx] = (node < N_NODES) ? x4[node * (INC / 4) + idx % (INC / 4)]
                                        : make_float4(0.f, 0.f, 0.f, 0.f);
        }
    }
    __syncthreads();

    int ct = t & 15;        // cols ct*4 .. ct*4+3
    int grp = t >> 4;       // nodes grp, grp+8, grp+16, grp+24
    unsigned long long acc[4][2];
#pragma unroll
    for (int n = 0; n < 4; n++) { acc[n][0] = 0ull; acc[n][1] = 0ull; }

#pragma unroll 4
    for (int k = 0; k < INC; k++) {
        unsigned long long w0 = *(const unsigned long long*)&Ws[k * OUTC + ct * 4];
        unsigned long long w1 = *(const unsigned long long*)&Ws[k * OUTC + ct * 4 + 2];
#pragma unroll
        for (int n = 0; n < 4; n++) {
            float xv = xs[grp + n * 8][k];
            unsigned long long xv2 = pack2(xv, xv);
            fma2(acc[n][0], xv2, w0, acc[n][0]);
            fma2(acc[n][1], xv2, w1, acc[n][1]);
        }
    }

#pragma unroll
    for (int n = 0; n < 4; n++) {
        int node = base + grp + n * 8;
        if (node < N_NODES) {
            float a, b;
            unpack2(a, b, acc[n][0]);
            float2* o0 = (float2*)&outp[node * OUTC + ct * 4];
            o0[0] = make_float2(a, b);
            unpack2(a, b, acc[n][1]);
            o0[1] = make_float2(a, b);
        }
    }
}

__device__ __forceinline__ float lrelu(float v) { return v > 0.0f ? v : 0.2f * v; }

// Warp per dst node: 8-wide unrolled online-softmax aggregation + epilogue.
__global__ void k_node(const float* __restrict__ att,
                       const float* __restrict__ bias,
                       float* __restrict__ out) {
    int n = (blockIdx.x * blockDim.x + threadIdx.x) >> 5;
    int lane = threadIdx.x & 31;
    if (n >= N_NODES) return;

    float a0 = att[lane], a1 = att[lane + 32];
    float xr0 = g_xr[n * OUTC + lane];
    float xr1 = g_xr[n * OUTC + 32 + lane];
    int e = g_off[n], end = g_off[n + 1];

    float m = -INFINITY, den = 0.0f, acc0 = 0.0f, acc1 = 0.0f;

    for (; e + 8 <= end; e += 8) {
        int s[8];
#pragma unroll
        for (int i = 0; i < 8; i++) s[i] = g_src[e + i];
        float xa[8], xb[8], tt[8];
#pragma unroll
        for (int i = 0; i < 8; i++) {
            xa[i] = g_xl[s[i] * OUTC + lane];
            xb[i] = g_xl[s[i] * OUTC + 32 + lane];
        }
#pragma unroll
        for (int i = 0; i < 8; i++)
            tt[i] = lrelu(xa[i] + xr0) * a0 + lrelu(xb[i] + xr1) * a1;
#pragma unroll
        for (int o = 16; o; o >>= 1) {
#pragma unroll
            for (int i = 0; i < 8; i++)
                tt[i] += __shfl_xor_sync(0xffffffffu, tt[i], o);
        }
        float bm = tt[0];
#pragma unroll
        for (int i = 1; i < 8; i++) bm = fmaxf(bm, tt[i]);
        float mn = fmaxf(m, bm);
        float sc = __expf(m - mn);       // first batch: __expf(-inf)=0
        float w[8], dsum = 0.f, s0 = 0.f, s1 = 0.f;
#pragma unroll
        for (int i = 0; i < 8; i++) {
            w[i] = __expf(tt[i] - mn);
            dsum += w[i];
            s0 += w[i] * xa[i];
            s1 += w[i] * xb[i];
        }
        den  = den  * sc + dsum;
        acc0 = acc0 * sc + s0;
        acc1 = acc1 * sc + s1;
        m = mn;
    }
    if (e + 4 <= end) {
        int s[4];
#pragma unroll
        for (int i = 0; i < 4; i++) s[i] = g_src[e + i];
        float xa[4], xb[4], tt[4];
#pragma unroll
        for (int i = 0; i < 4; i++) {
            xa[i] = g_xl[s[i] * OUTC + lane];
            xb[i] = g_xl[s[i] * OUTC + 32 + lane];
        }
#pragma unroll
        for (int i = 0; i < 4; i++)
            tt[i] = lrelu(xa[i] + xr0) * a0 + lrelu(xb[i] + xr1) * a1;
#pragma unroll
        for (int o = 16; o; o >>= 1) {
#pragma unroll
            for (int i = 0; i < 4; i++)
                tt[i] += __shfl_xor_sync(0xffffffffu, tt[i], o);
        }
        float bm = fmaxf(fmaxf(tt[0], tt[1]), fmaxf(tt[2], tt[3]));
        float mn = fmaxf(m, bm);
        float sc = __expf(m - mn);
        float w0 = __expf(tt[0] - mn), w1 = __expf(tt[1] - mn);
        float w2 = __expf(tt[2] - mn), w3 = __expf(tt[3] - mn);
        den  = den  * sc + ((w0 + w1) + (w2 + w3));
        acc0 = acc0 * sc + (w0 * xa[0] + w1 * xa[1] + w2 * xa[2] + w3 * xa[3]);
        acc1 = acc1 * sc + (w0 * xb[0] + w1 * xb[1] + w2 * xb[2] + w3 * xb[3]);
        m = mn;
        e += 4;
    }
    for (; e < end; e++) {
        int s = g_src[e];
        float xl0 = g_xl[s * OUTC + lane];
        float xl1 = g_xl[s * OUTC + 32 + lane];
        float t0 = lrelu(xl0 + xr0) * a0 + lrelu(xl1 + xr1) * a1;
#pragma unroll
        for (int o = 16; o; o >>= 1) t0 += __shfl_xor_sync(0xffffffffu, t0, o);
        float mn = fmaxf(m, t0);
        float sc = __expf(m - mn);
        float w  = __expf(t0 - mn);
        den  = den  * sc + w;
        acc0 = acc0 * sc + w * xl0;
        acc1 = acc1 * sc + w * xl1;
        m = mn;
    }

    float inv = 1.0f / den;              // den>0: self-loop guarantees an edge
    float h0 = acc0 * inv + bias[lane];
    float h1 = acc1 * inv + bias[lane + 32];
    h0 = h0 > 0.0f ? h0 : __expf(h0) - 1.0f;
    h1 = h1 > 0.0f ? h1 : __expf(h1) - 1.0f;
    float mx = fmaxf(h0, h1);
#pragma unroll
    for (int o = 16; o; o >>= 1) mx = fmaxf(mx, __shfl_xor_sync(0xffffffffu, mx, o));
    float sme = __expf(h0 - mx) + __expf(h1 - mx);
#pragma unroll
    for (int o = 16; o; o >>= 1) sme += __shfl_xor_sync(0xffffffffu, sme, o);
    float ls = mx + __logf(sme);
    out[n * OUTC + lane]      = h0 - ls;
    out[n * OUTC + 32 + lane] = h1 - ls;
}

extern "C" void kernel_launch(void* const* d_in, const int* in_sizes, int n_in,
                              void* d_out, int out_size) {
    const float* x    = (const float*)d_in[0];
    const int*   ei   = (const int*)d_in[1];   // int32 (JAX x64 disabled)
    const float* Wl   = (const float*)d_in[2];
    const float* Wr   = (const float*)d_in[3];
    const float* att  = (const float*)d_in[4];
    const float* bias = (const float*)d_in[5];
    float*       out  = (float*)d_out;

    // Linear order on default stream; k_gemm placed 4th (ncu capture slot).
    {
        int thr = (TOT_E + 3) / 4;
        k_hist<<<(thr + 255) / 256, 256>>>(ei);
    }
    k_part<<<NBLK, 256>>>();
    k_bscan<<<1, 256>>>();
    {
        dim3 grid((N_NODES + GN - 1) / GN, 2);
        k_gemm<<<grid, 128>>>(x, Wl, Wr);
    }
    k_off<<<NBLK, 256>>>();
    {
        int thr = (TOT_E + 3) / 4;
        k_scatter<<<(thr + 255) / 256, 256>>>(ei);
    }
    k_node<<<(N_NODES * 32 + 255) / 256, 256>>>(att, bias, out);
}

// round 17
// speedup vs baseline: 2.8797x; 1.0345x over previous
#include <cuda_runtime.h>
#include <math.h>

#define N_NODES 50000
#define N_EDGES 800000
#define INC 128
#define OUTC 64
#define TOT_E (N_EDGES + N_NODES)
#define NBLK ((N_NODES + 255) / 256)   // 196 scan blocks
#define GN 64                          // gemm nodes per block

// Scratch (__device__ globals per allocation-free contract)
__device__ float g_xl[N_NODES * OUTC];   // 12.8 MB
__device__ float g_xr[N_NODES * OUTC];   // 12.8 MB
__device__ int   g_deg[N_NODES];         // zero-init at load; re-zeroed by k_off
__device__ int   g_off[N_NODES + 1];
__device__ int   g_cur[N_NODES];
__device__ int   g_src[TOT_E];           // CSR: source ids grouped by dst
__device__ int   g_bsum[NBLK];
__device__ int   g_boff[NBLK];

// Degree histogram over dst, 4 independent edges per thread for MLP.
__global__ void k_hist(const int* __restrict__ ei) {
    int t = blockIdx.x * blockDim.x + threadIdx.x;
    int stride = gridDim.x * blockDim.x;
#pragma unroll
    for (int i = 0; i < 4; i++) {
        int e = t + i * stride;
        if (e < TOT_E) {
            int d = (e < N_EDGES) ? ei[N_EDGES + e] : (e - N_EDGES);
            atomicAdd(&g_deg[d], 1);
        }
    }
}

// ---- chip-wide 3-phase exclusive scan of g_deg -> g_off ----
__global__ void k_part() {
    int i = blockIdx.x * 256 + threadIdx.x;
    int lane = threadIdx.x & 31, wid = threadIdx.x >> 5;
    int v = (i < N_NODES) ? g_deg[i] : 0;
#pragma unroll
    for (int o = 16; o; o >>= 1) v += __shfl_xor_sync(0xffffffffu, v, o);
    __shared__ int ws[8];
    if (lane == 0) ws[wid] = v;
    __syncthreads();
    if (threadIdx.x == 0) {
        int s = 0;
#pragma unroll
        for (int w = 0; w < 8; w++) s += ws[w];
        g_bsum[blockIdx.x] = s;
    }
}

__global__ void k_bscan() {
    int t = threadIdx.x;
    int lane = t & 31, wid = t >> 5;
    int v = (t < NBLK) ? g_bsum[t] : 0;
    int incl = v;
#pragma unroll
    for (int o = 1; o < 32; o <<= 1) {
        int u = __shfl_up_sync(0xffffffffu, incl, o);
        if (lane >= o) incl += u;
    }
    __shared__ int ws[8];
    if (lane == 31) ws[wid] = incl;
    __syncthreads();
    int woff = 0;
#pragma unroll
    for (int w = 0; w < 8; w++) woff += (w < wid) ? ws[w] : 0;
    int excl = woff + incl - v;
    if (t < NBLK) g_boff[t] = excl;
    if (t == NBLK - 1) g_off[N_NODES] = excl + v;
}

// Phase 3: offsets; also re-zeroes g_deg for the next graph replay.
__global__ void k_off() {
    int i = blockIdx.x * 256 + threadIdx.x;
    int lane = threadIdx.x & 31, wid = threadIdx.x >> 5;
    int v = (i < N_NODES) ? g_deg[i] : 0;
    int incl = v;
#pragma unroll
    for (int o = 1; o < 32; o <<= 1) {
        int u = __shfl_up_sync(0xffffffffu, incl, o);
        if (lane >= o) incl += u;
    }
    __shared__ int ws[8];
    if (lane == 31) ws[wid] = incl;
    __syncthreads();
    int woff = 0;
#pragma unroll
    for (int w = 0; w < 8; w++) woff += (w < wid) ? ws[w] : 0;
    int excl = g_boff[blockIdx.x] + woff + incl - v;
    if (i < N_NODES) {
        g_off[i] = excl;
        g_cur[i] = excl;
        g_deg[i] = 0;          // ready for next replay's k_hist
    }
}

// Scatter src ids by dst, 4 independent edges per thread.
__global__ void k_scatter(const int* __restrict__ ei) {
    int t = blockIdx.x * blockDim.x + threadIdx.x;
    int stride = gridDim.x * blockDim.x;
#pragma unroll
    for (int i = 0; i < 4; i++) {
        int e = t + i * stride;
        if (e < TOT_E) {
            int s, d;
            if (e < N_EDGES) { s = ei[e]; d = ei[N_EDGES + e]; }
            else             { s = e - N_EDGES; d = s; }
            int pos = atomicAdd(&g_cur[d], 1);
            g_src[pos] = s;
        }
    }
}

// Packed fp32x2 FMA (sm_103a FFMA2) helpers
__device__ __forceinline__ void fma2(unsigned long long& d,
                                     unsigned long long a,
                                     unsigned long long b,
                                     unsigned long long c) {
    asm("fma.rn.f32x2 %0, %1, %2, %3;" : "=l"(d) : "l"(a), "l"(b), "l"(c));
}
__device__ __forceinline__ unsigned long long pack2(float lo, float hi) {
    unsigned long long r;
    asm("mov.b64 %0, {%1, %2};" : "=l"(r) : "f"(lo), "f"(hi));
    return r;
}
__device__ __forceinline__ void unpack2(float& lo, float& hi, unsigned long long v) {
    asm("mov.b64 {%0, %1}, %2;" : "=f"(lo), "=f"(hi) : "l"(v));
}

// Transform: grid (ceil(N/GN), 2); y=0 -> W_l/g_xl, y=1 -> W_r/g_xr.
// 256 threads: 16 col-threads (4 cols) x 16 groups (4 nodes each: grp+{0,16,32,48}).
// W staged in smem (read as ulonglong2 = one LDS.128 -> both f32x2 operands);
// x read directly from global as float4 (same addr across 16 lanes -> broadcast).
__global__ void k_gemm(const float* __restrict__ x,
                       const float* __restrict__ Wl,
                       const float* __restrict__ Wr) {
    __shared__ float Ws[INC * OUTC];     // 32 KB
    const float* W = blockIdx.y ? Wr : Wl;
    float* outp = blockIdx.y ? g_xr : g_xl;
    int t = threadIdx.x;
    int base = blockIdx.x * GN;

    {   // stage W (8192 floats) via float4
        const float4* W4 = (const float4*)W;
        float4* Ws4 = (float4*)Ws;
#pragma unroll
        for (int i = 0; i < (INC * OUTC / 4) / 256; i++)
            Ws4[t + i * 256] = W4[t + i * 256];
    }
    __syncthreads();

    int ct = t & 15;        // cols ct*4 .. ct*4+3
    int grp = t >> 4;       // 0..15
    int nd[4];
#pragma unroll
    for (int i = 0; i < 4; i++) {
        int nn = base + grp + i * 16;
        nd[i] = (nn < N_NODES) ? nn : 0;   // clamp; store is guarded
    }

    unsigned long long acc[4][2];
#pragma unroll
    for (int i = 0; i < 4; i++) { acc[i][0] = 0ull; acc[i][1] = 0ull; }

    const float4* x4 = (const float4*)x;           // row = 32 float4

#pragma unroll 4
    for (int kq = 0; kq < INC / 4; kq++) {
        float4 xv[4];
#pragma unroll
        for (int i = 0; i < 4; i++)
            xv[i] = __ldg(&x4[nd[i] * (INC / 4) + kq]);
#pragma unroll
        for (int kk = 0; kk < 4; kk++) {
            ulonglong2 w = *(const ulonglong2*)&Ws[(kq * 4 + kk) * OUTC + ct * 4];
#pragma unroll
            for (int i = 0; i < 4; i++) {
                float xs = (kk == 0) ? xv[i].x : (kk == 1) ? xv[i].y
                         : (kk == 2) ? xv[i].z : xv[i].w;
                unsigned long long x2 = pack2(xs, xs);
                fma2(acc[i][0], x2, w.x, acc[i][0]);
                fma2(acc[i][1], x2, w.y, acc[i][1]);
            }
        }
    }

#pragma unroll
    for (int i = 0; i < 4; i++) {
        int nn = base + grp + i * 16;
        if (nn < N_NODES) {
            float a, b, c, d;
            unpack2(a, b, acc[i][0]);
            unpack2(c, d, acc[i][1]);
            *(float4*)&outp[nn * OUTC + ct * 4] = make_float4(a, b, c, d);
        }
    }
}

__device__ __forceinline__ float lrelu(float v) { return v > 0.0f ? v : 0.2f * v; }

// Warp per dst node: 8-wide unrolled online-softmax aggregation + epilogue.
__global__ void k_node(const float* __restrict__ att,
                       const float* __restrict__ bias,
                       float* __restrict__ out) {
    int n = (blockIdx.x * blockDim.x + threadIdx.x) >> 5;
    int lane = threadIdx.x & 31;
    if (n >= N_NODES) return;

    float a0 = att[lane], a1 = att[lane + 32];
    float xr0 = g_xr[n * OUTC + lane];
    float xr1 = g_xr[n * OUTC + 32 + lane];
    int e = g_off[n], end = g_off[n + 1];

    float m = -INFINITY, den = 0.0f, acc0 = 0.0f, acc1 = 0.0f;

    for (; e + 8 <= end; e += 8) {
        int s[8];
#pragma unroll
        for (int i = 0; i < 8; i++) s[i] = g_src[e + i];
        float xa[8], xb[8], tt[8];
#pragma unroll
        for (int i = 0; i < 8; i++) {
            xa[i] = g_xl[s[i] * OUTC + lane];
            xb[i] = g_xl[s[i] * OUTC + 32 + lane];
        }
#pragma unroll
        for (int i = 0; i < 8; i++)
            tt[i] = lrelu(xa[i] + xr0) * a0 + lrelu(xb[i] + xr1) * a1;
#pragma unroll
        for (int o = 16; o; o >>= 1) {
#pragma unroll
            for (int i = 0; i < 8; i++)
                tt[i] += __shfl_xor_sync(0xffffffffu, tt[i], o);
        }
        float bm = tt[0];
#pragma unroll
        for (int i = 1; i < 8; i++) bm = fmaxf(bm, tt[i]);
        float mn = fmaxf(m, bm);
        float sc = __expf(m - mn);       // first batch: __expf(-inf)=0
        float w[8], dsum = 0.f, s0 = 0.f, s1 = 0.f;
#pragma unroll
        for (int i = 0; i < 8; i++) {
            w[i] = __expf(tt[i] - mn);
            dsum += w[i];
            s0 += w[i] * xa[i];
            s1 += w[i] * xb[i];
        }
        den  = den  * sc + dsum;
        acc0 = acc0 * sc + s0;
        acc1 = acc1 * sc + s1;
        m = mn;
    }
    if (e + 4 <= end) {
        int s[4];
#pragma unroll
        for (int i = 0; i < 4; i++) s[i] = g_src[e + i];
        float xa[4], xb[4], tt[4];
#pragma unroll
        for (int i = 0; i < 4; i++) {
            xa[i] = g_xl[s[i] * OUTC + lane];
            xb[i] = g_xl[s[i] * OUTC + 32 + lane];
        }
#pragma unroll
        for (int i = 0; i < 4; i++)
            tt[i] = lrelu(xa[i] + xr0) * a0 + lrelu(xb[i] + xr1) * a1;
#pragma unroll
        for (int o = 16; o; o >>= 1) {
#pragma unroll
            for (int i = 0; i < 4; i++)
                tt[i] += __shfl_xor_sync(0xffffffffu, tt[i], o);
        }
        float bm = fmaxf(fmaxf(tt[0], tt[1]), fmaxf(tt[2], tt[3]));
        float mn = fmaxf(m, bm);
        float sc = __expf(m - mn);
        float w0 = __expf(tt[0] - mn), w1 = __expf(tt[1] - mn);
        float w2 = __expf(tt[2] - mn), w3 = __expf(tt[3] - mn);
        den  = den  * sc + ((w0 + w1) + (w2 + w3));
        acc0 = acc0 * sc + (w0 * xa[0] + w1 * xa[1] + w2 * xa[2] + w3 * xa[3]);
        acc1 = acc1 * sc + (w0 * xb[0] + w1 * xb[1] + w2 * xb[2] + w3 * xb[3]);
        m = mn;
        e += 4;
    }
    for (; e < end; e++) {
        int s = g_src[e];
        float xl0 = g_xl[s * OUTC + lane];
        float xl1 = g_xl[s * OUTC + 32 + lane];
        float t0 = lrelu(xl0 + xr0) * a0 + lrelu(xl1 + xr1) * a1;
#pragma unroll
        for (int o = 16; o; o >>= 1) t0 += __shfl_xor_sync(0xffffffffu, t0, o);
        float mn = fmaxf(m, t0);
        float sc = __expf(m - mn);
        float w  = __expf(t0 - mn);
        den  = den  * sc + w;
        acc0 = acc0 * sc + w * xl0;
        acc1 = acc1 * sc + w * xl1;
        m = mn;
    }

    float inv = 1.0f / den;              // den>0: self-loop guarantees an edge
    float h0 = acc0 * inv + bias[lane];
    float h1 = acc1 * inv + bias[lane + 32];
    h0 = h0 > 0.0f ? h0 : __expf(h0) - 1.0f;
    h1 = h1 > 0.0f ? h1 : __expf(h1) - 1.0f;
    float mx = fmaxf(h0, h1);
#pragma unroll
    for (int o = 16; o; o >>= 1) mx = fmaxf(mx, __shfl_xor_sync(0xffffffffu, mx, o));
    float sme = __expf(h0 - mx) + __expf(h1 - mx);
#pragma unroll
    for (int o = 16; o; o >>= 1) sme += __shfl_xor_sync(0xffffffffu, sme, o);
    float ls = mx + __logf(sme);
    out[n * OUTC + lane]      = h0 - ls;
    out[n * OUTC + 32 + lane] = h1 - ls;
}

extern "C" void kernel_launch(void* const* d_in, const int* in_sizes, int n_in,
                              void* d_out, int out_size) {
    const float* x    = (const float*)d_in[0];
    const int*   ei   = (const int*)d_in[1];   // int32 (JAX x64 disabled)
    const float* Wl   = (const float*)d_in[2];
    const float* Wr   = (const float*)d_in[3];
    const float* att  = (const float*)d_in[4];
    const float* bias = (const float*)d_in[5];
    float*       out  = (float*)d_out;

    // One-time resources (host-side objects only; no device memory).
    static cudaStream_t s2 = 0;
    static cudaEvent_t evA = 0, evB = 0;
    if (!s2) {
        cudaStreamCreateWithFlags(&s2, cudaStreamNonBlocking);
        cudaEventCreateWithFlags(&evA, cudaEventDisableTiming);
        cudaEventCreateWithFlags(&evB, cudaEventDisableTiming);
    }

    // Fork: gemm on s2 overlaps the CSR build on the main stream.
    cudaEventRecord(evA, 0);
    cudaStreamWaitEvent(s2, evA, 0);
    {
        dim3 grid((N_NODES + GN - 1) / GN, 2);
        k_gemm<<<grid, 256, 0, s2>>>(x, Wl, Wr);
    }
    cudaEventRecord(evB, s2);

    {
        int thr = (TOT_E + 3) / 4;
        k_hist<<<(thr + 255) / 256, 256>>>(ei);
    }
    k_part<<<NBLK, 256>>>();
    k_bscan<<<1, 256>>>();
    k_off<<<NBLK, 256>>>();
    {
        int thr = (TOT_E + 3) / 4;
        k_scatter<<<(thr + 255) / 256, 256>>>(ei);
    }

    // Join, then fused node kernel.
    cudaStreamWaitEvent(0, evB, 0);
    k_node<<<(N_NODES * 32 + 255) / 256, 256>>>(att, bias, out);
}